// round 17
// baseline (speedup 1.0000x reference)
#include <cuda_runtime.h>
#include <cstdint>

typedef unsigned long long u64;
typedef unsigned int u32;
#define FULL 0xFFFFFFFFu

__device__ __forceinline__ float ex2(float x){
    float r; asm("ex2.approx.f32 %0,%1;" : "=f"(r) : "f"(x)); return r;
}
__device__ __forceinline__ float frcp(float x){
    float r; asm("rcp.approx.f32 %0,%1;" : "=f"(r) : "f"(x)); return r;
}
__device__ __forceinline__ u32 totf32(float x){
    u32 r; asm("cvt.rna.tf32.f32 %0,%1;" : "=r"(r) : "f"(x)); return r;
}
__device__ __forceinline__ void cpa16(u32 dst, const void* src){
    asm volatile("cp.async.cg.shared.global [%0], [%1], 16;" :: "r"(dst), "l"(src));
}
__device__ __forceinline__ void cp_commit(){ asm volatile("cp.async.commit_group;"); }
__device__ __forceinline__ void cp_wait2(){ asm volatile("cp.async.wait_group 2;"); }
__device__ __forceinline__ void cp_wait1(){ asm volatile("cp.async.wait_group 1;"); }
__device__ __forceinline__ void cp_wait0(){ asm volatile("cp.async.wait_group 0;"); }

#define BAR_PAIR(id) asm volatile("bar.sync %0, 64;" :: "r"(id) : "memory")

// per-CTA partials: [bh*4 + q4]
__device__ float g_Mp[512 * 4096];
__device__ float g_Sp[512 * 64];

__device__ __forceinline__ float get_cT(const float* __restrict__ delta){
    float d = delta[0];
    float t = (d > 20.f) ? d : log1pf(expf(d));
    return 1.44269504088896f / t;
}

#define MMA_TF32(C, a0,a1,a2,a3, b0,b1) \
    asm("mma.sync.aligned.m16n8k8.row.col.f32.tf32.tf32.f32 " \
        "{%0,%1,%2,%3},{%4,%5,%6,%7},{%8,%9},{%0,%1,%2,%3};" \
        : "+f"((C)[0]),"+f"((C)[1]),"+f"((C)[2]),"+f"((C)[3]) \
        : "r"(a0),"r"(a1),"r"(a2),"r"(a3), "r"(b0),"r"(b1))

// =====================================================================
// kv_mma: unchanged from round 16 (32-row tiles, 3-stage pipeline).
// =====================================================================
#define KV_SMEM (13824 * 4)

__global__ __launch_bounds__(128, 4) void kv_mma(
    const float* __restrict__ Kp, const float* __restrict__ Vp,
    const float* __restrict__ delta)
{
    extern __shared__ float pool[];

    const int bx   = blockIdx.x;
    const int bh   = bx >> 2;
    const int b    = bh >> 4, h = bh & 15;
    const int tid  = threadIdx.x;
    const int w    = tid >> 5, lane = tid & 31;
    const int g    = lane >> 2, tig = lane & 3;

    const float cT = get_cT(delta);
    const long cbase = ((long)b * 4096L) * 1024L + h * 64L;
    const float* kglob = Kp + cbase;
    const float* vglob = Vp + cbase;
    const long Lbase = (long)(bx & 3) * 1024;

    const u32 sb = (u32)__cvta_generic_to_shared(pool);

    for (int idx = tid; idx < 768; idx += 128){
        int bf3 = idx >> 8, rem = idx & 255;
        int row = rem >> 3, col = 64 + (rem & 7);
        pool[6912 + bf3 * 2304 + row * 72 + col] = (col == 64) ? 1.f : 0.f;
    }
    __syncthreads();

    float C[4][3][4];
    #pragma unroll
    for (int mt = 0; mt < 4; mt++)
        #pragma unroll
        for (int nt = 0; nt < 3; nt++)
            #pragma unroll
            for (int i = 0; i < 4; i++) C[mt][nt][i] = 0.f;
    const int nts = (w == 3) ? 3 : 2;
    const int e0  = w * 16;

    auto load_tile = [&](int t, int bf3){
        const long l0 = Lbase + (long)t * 32;
        const float* src = (w < 2) ? kglob : vglob;
        const u32 dbase = sb + ((w < 2 ? 0 : 6912) + bf3 * 2304) * 4;
        const int rbase = (w & 1) * 16;
        #pragma unroll
        for (int i = 0; i < 8; i++){
            int slot = lane + 32 * i;
            int r = rbase + (slot >> 4);
            int ch = slot & 15;
            cpa16(dbase + (u32)(r * 72 + ch * 4) * 4, src + (l0 + r) * 1024 + ch * 4);
        }
        cp_commit();
    };

    load_tile(0, 0);
    load_tile(1, 1);

    for (int t = 0; t < 32; t++){
        __syncthreads();
        if (t + 2 < 32){ load_tile(t + 2, (t + 2) % 3); cp_wait2(); }
        else if (t + 1 < 32) cp_wait1();
        else cp_wait0();
        __syncthreads();

        float* kbuf = pool + (t % 3) * 2304;
        const float* vbuf = pool + 6912 + (t % 3) * 2304;

        {
            const int row = tid >> 2, sub = tid & 3;
            float* rowp = kbuf + row * 72 + sub * 16;
            float4 fa = *(float4*)rowp;
            float4 fb = *(float4*)(rowp + 4);
            float4 fc = *(float4*)(rowp + 8);
            float4 fd = *(float4*)(rowp + 12);
            float v0 = ex2(cT * ((fa.x < 0.f) ? -20.f : fa.x));
            float v1 = ex2(cT * ((fa.y < 0.f) ? -20.f : fa.y));
            float v2 = ex2(cT * ((fa.z < 0.f) ? -20.f : fa.z));
            float v3 = ex2(cT * ((fa.w < 0.f) ? -20.f : fa.w));
            float v4 = ex2(cT * ((fb.x < 0.f) ? -20.f : fb.x));
            float v5 = ex2(cT * ((fb.y < 0.f) ? -20.f : fb.y));
            float v6 = ex2(cT * ((fb.z < 0.f) ? -20.f : fb.z));
            float v7 = ex2(cT * ((fb.w < 0.f) ? -20.f : fb.w));
            float v8 = ex2(cT * ((fc.x < 0.f) ? -20.f : fc.x));
            float v9 = ex2(cT * ((fc.y < 0.f) ? -20.f : fc.y));
            float vA = ex2(cT * ((fc.z < 0.f) ? -20.f : fc.z));
            float vB = ex2(cT * ((fc.w < 0.f) ? -20.f : fc.w));
            float vC = ex2(cT * ((fd.x < 0.f) ? -20.f : fd.x));
            float vD = ex2(cT * ((fd.y < 0.f) ? -20.f : fd.y));
            float vE = ex2(cT * ((fd.z < 0.f) ? -20.f : fd.z));
            float vF = ex2(cT * ((fd.w < 0.f) ? -20.f : fd.w));
            float sm = (((v0 + v1) + (v2 + v3)) + ((v4 + v5) + (v6 + v7)))
                     + (((v8 + v9) + (vA + vB)) + ((vC + vD) + (vE + vF)));
            sm += __shfl_xor_sync(FULL, sm, 1);
            sm += __shfl_xor_sync(FULL, sm, 2);
            float rs = frcp(sm);
            uint4 oa, ob, oc, od;
            oa.x = totf32(v0 * rs); oa.y = totf32(v1 * rs);
            oa.z = totf32(v2 * rs); oa.w = totf32(v3 * rs);
            ob.x = totf32(v4 * rs); ob.y = totf32(v5 * rs);
            ob.z = totf32(v6 * rs); ob.w = totf32(v7 * rs);
            oc.x = totf32(v8 * rs); oc.y = totf32(v9 * rs);
            oc.z = totf32(vA * rs); oc.w = totf32(vB * rs);
            od.x = totf32(vC * rs); od.y = totf32(vD * rs);
            od.z = totf32(vE * rs); od.w = totf32(vF * rs);
            *(uint4*)rowp        = oa;
            *(uint4*)(rowp + 4)  = ob;
            *(uint4*)(rowp + 8)  = oc;
            *(uint4*)(rowp + 12) = od;
        }
        __syncthreads();

        {
            const u32* kB = (const u32*)kbuf;
            u32 bf[4][3][2];
            #pragma unroll
            for (int kt = 0; kt < 4; kt++)
                #pragma unroll
                for (int nt = 0; nt < 3; nt++)
                    if (nt < nts){
                        float b0 = vbuf[(kt * 8 + tig) * 72 + e0 + nt * 8 + g];
                        float b1 = vbuf[(kt * 8 + tig + 4) * 72 + e0 + nt * 8 + g];
                        bf[kt][nt][0] = totf32(b0);
                        bf[kt][nt][1] = totf32(b1);
                    }
            #pragma unroll
            for (int mt = 0; mt < 4; mt++){
                #pragma unroll
                for (int kt = 0; kt < 4; kt++){
                    u32 a0 = kB[(kt * 8 + tig) * 72 + mt * 16 + g];
                    u32 a1 = kB[(kt * 8 + tig) * 72 + mt * 16 + g + 8];
                    u32 a2 = kB[(kt * 8 + tig + 4) * 72 + mt * 16 + g];
                    u32 a3 = kB[(kt * 8 + tig + 4) * 72 + mt * 16 + g + 8];
                    #pragma unroll
                    for (int nt = 0; nt < 3; nt++)
                        if (nt < nts) MMA_TF32(C[mt][nt], a0, a1, a2, a3,
                                               bf[kt][nt][0], bf[kt][nt][1]);
                }
            }
        }
    }

    float* Mp = g_Mp + (long)bx * 4096;
    #pragma unroll
    for (int mt = 0; mt < 4; mt++){
        #pragma unroll
        for (int nt = 0; nt < 3; nt++){
            if (nt >= nts) continue;
            if (w == 3 && nt == 2){
                if (tig == 0){
                    g_Sp[bx * 64 + mt * 16 + g]     = C[mt][2][0];
                    g_Sp[bx * 64 + mt * 16 + g + 8] = C[mt][2][2];
                }
            } else {
                const int e = e0 + nt * 8 + 2 * tig;
                *(float2*)(Mp + (mt * 16 + g) * 64 + e)
                    = make_float2(C[mt][nt][0], C[mt][nt][1]);
                *(float2*)(Mp + (mt * 16 + g + 8) * 64 + e)
                    = make_float2(C[mt][nt][2], C[mt][nt][3]);
            }
        }
    }
}

// =====================================================================
// out_mma v7: e-split warp pairs for occupancy. Pair p (warps 2p,2p+1)
// shares a 16-row tile stream (3-stage, cooperative loads, 2 named
// barriers/tile); each warp does full fused softmax but only its
// 32-col e-half -> BF[8][4][2] = 64 regs -> 3 CTAs/SM (12 warps/SM).
// grid 1024 (8 CTAs/bh, 512 rows = 16 tiles of 32 = per pair 16x16).
// Dyn smem: sM f[64*68] | pbuf f[2][3][16][68] | sSh f[64]  (~44 KB).
// =====================================================================
#define SM_BYTES    17408
#define PBUF_BYTES  26112
#define OUT_SMEM    (SM_BYTES + PBUF_BYTES + 256)

__global__ __launch_bounds__(128, 3) void out_mma(
    const float* __restrict__ Qp, float* __restrict__ Out,
    const float* __restrict__ delta)
{
    extern __shared__ char osm[];
    float* sM   = (float*)osm;                          // [64*68], init only
    float* pall = (float*)(osm + SM_BYTES);             // [2][3][1088]
    float* sSh  = (float*)(osm + SM_BYTES + PBUF_BYTES);

    const int bx   = blockIdx.x;
    const int bh   = bx >> 3;
    const int b    = bh >> 4, h = bh & 15;
    const int tid  = threadIdx.x;
    const int w    = tid >> 5, lane = tid & 31;
    const int g    = lane >> 2, tig = lane & 3;
    const int p    = w >> 1, hf = w & 1;
    const int e0   = 32 * hf;

    const float cT = get_cT(delta);
    const long cbase = ((long)b * 4096L) * 1024L + h * 64L;
    const long Lbase = (long)(bx & 7) * 512;

    float* pbuf = pall + p * 3264;                      // pair's 3 buffers
    const u32 pb = (u32)__cvta_generic_to_shared(pbuf);

    // cooperative pair load: warp hf loads rows [8hf, 8hf+8) of the tile
    auto load_tile = [&](int t, int buf){
        const long l0 = Lbase + (long)t * 32 + 16 * p + 8 * hf;
        const u32 dbase = pb + (u32)(buf * 1088 + 8 * hf * 68) * 4;
        #pragma unroll
        for (int i = 0; i < 4; i++){
            int slot = lane + 32 * i;          // 0..127
            int r = slot >> 4, ch = slot & 15;
            cpa16(dbase + (u32)(r * 68 + ch * 4) * 4, Qp + cbase + (l0 + r) * 1024 + ch * 4);
        }
        cp_commit();
    };

    load_tile(0, 0);   // overlap M init
    load_tile(1, 1);

    if (tid < 64){
        float s = 0.f;
        #pragma unroll
        for (int q = 0; q < 4; q++) s += g_Sp[(bh * 4 + q) * 64 + tid];
        sSh[tid] = s;
    }
    for (int i = tid; i < 1024; i += 128){
        const int d = i >> 4, c4 = (i & 15) * 4;
        float4 a = make_float4(0.f, 0.f, 0.f, 0.f);
        #pragma unroll
        for (int q = 0; q < 4; q++){
            float4 v = *(const float4*)(g_Mp + (long)(bh * 4 + q) * 4096 + d * 64 + c4);
            a.x += v.x; a.y += v.y; a.z += v.z; a.w += v.w;
        }
        *(float4*)(sM + d * 68 + c4) = a;
    }
    __syncthreads();   // sM/sSh ready (never recycled — last block barrier)

    u32 BF[8][4][2];
    #pragma unroll
    for (int kt = 0; kt < 8; kt++)
        #pragma unroll
        for (int nt = 0; nt < 4; nt++){
            BF[kt][nt][0] = totf32(sM[(kt * 8 + tig)     * 68 + e0 + nt * 8 + g]);
            BF[kt][nt][1] = totf32(sM[(kt * 8 + tig + 4) * 68 + e0 + nt * 8 + g]);
        }
    float s_reg[16];
    #pragma unroll
    for (int j = 0; j < 16; j++) s_reg[j] = sSh[tig + 4 * j];

    for (int t = 0; t < 16; t++){
        BAR_PAIR(1 + p);                       // pair done consuming tile t-1
        if (t + 2 < 16){ load_tile(t + 2, (t + 2) % 3); cp_wait2(); }
        else if (t + 1 < 16) cp_wait1();
        else cp_wait0();
        BAR_PAIR(1 + p);                       // both halves of tile t resident

        const float* r0p = pbuf + (t % 3) * 1088 + g * 68;
        const float* r1p = r0p + 8 * 68;

        float C[4][4];
        #pragma unroll
        for (int nt = 0; nt < 4; nt++)
            #pragma unroll
            for (int i = 0; i < 4; i++) C[nt][i] = 0.f;

        float sm0 = 0.f, u0 = 0.f, sm1 = 0.f, u1 = 0.f;

        #pragma unroll
        for (int kt = 0; kt < 8; kt++){
            float x0 = r0p[kt * 8 + tig];
            float x1 = r1p[kt * 8 + tig];
            float x2 = r0p[kt * 8 + tig + 4];
            float x3 = r1p[kt * 8 + tig + 4];
            float e0v = ex2(cT * ((x0 < 0.f) ? -20.f : x0));
            float e1v = ex2(cT * ((x1 < 0.f) ? -20.f : x1));
            float e2v = ex2(cT * ((x2 < 0.f) ? -20.f : x2));
            float e3v = ex2(cT * ((x3 < 0.f) ? -20.f : x3));
            sm0 += e0v + e2v;
            sm1 += e1v + e3v;
            u0 = fmaf(e0v, s_reg[2 * kt], fmaf(e2v, s_reg[2 * kt + 1], u0));
            u1 = fmaf(e1v, s_reg[2 * kt], fmaf(e3v, s_reg[2 * kt + 1], u1));
            u32 a0 = totf32(e0v), a1 = totf32(e1v);
            u32 a2 = totf32(e2v), a3 = totf32(e3v);
            #pragma unroll
            for (int nt = 0; nt < 4; nt++)
                MMA_TF32(C[nt], a0, a1, a2, a3, BF[kt][nt][0], BF[kt][nt][1]);
        }

        #pragma unroll
        for (int o = 1; o <= 2; o <<= 1){
            sm0 += __shfl_xor_sync(FULL, sm0, o);
            u0  += __shfl_xor_sync(FULL, u0,  o);
            sm1 += __shfl_xor_sync(FULL, sm1, o);
            u1  += __shfl_xor_sync(FULL, u1,  o);
        }
        const float gv0 = frcp(u0 + 1e-6f * sm0);
        const float gv1 = frcp(u1 + 1e-6f * sm1);

        const long l0 = Lbase + (long)t * 32 + 16 * p;
        float* o0 = Out + cbase + (l0 + g) * 1024 + e0 + 2 * tig;
        float* o1 = Out + cbase + (l0 + g + 8) * 1024 + e0 + 2 * tig;
        #pragma unroll
        for (int nt = 0; nt < 4; nt++){
            *(float2*)(o0 + nt * 8) = make_float2(C[nt][0] * gv0, C[nt][1] * gv0);
            *(float2*)(o1 + nt * 8) = make_float2(C[nt][2] * gv1, C[nt][3] * gv1);
        }
    }
}

extern "C" void kernel_launch(void* const* d_in, const int* in_sizes, int n_in,
                              void* d_out, int out_size)
{
    const float* Q     = (const float*)d_in[0];
    const float* K     = (const float*)d_in[1];
    const float* V     = (const float*)d_in[2];
    const float* delta = (const float*)d_in[3];
    float* Out = (float*)d_out;

    cudaFuncSetAttribute(kv_mma, cudaFuncAttributeMaxDynamicSharedMemorySize, KV_SMEM / 4 * 4);
    kv_mma<<<512, 128, 13824 * 4>>>(K, V, delta);
    cudaFuncSetAttribute(out_mma, cudaFuncAttributeMaxDynamicSharedMemorySize, OUT_SMEM);
    out_mma<<<1024, 128, OUT_SMEM>>>(Q, Out, delta);
}